// round 3
// baseline (speedup 1.0000x reference)
#include <cuda_runtime.h>

#define LD   128   // latent dims
#define NE   256   // num embeddings
#define MT   128   // rows per CTA
#define NCH  128   // embeddings per chunk
#define ES   129   // e smem row stride (floats) - odd stride => conflict-free scalar LDS

__device__ float g_esq[NE];

// ---------------------------------------------------------------------------
// esq_kernel: esq[k] = sum_d e[k][d]^2   (one tiny kernel, 1 block)
// ---------------------------------------------------------------------------
__global__ void esq_kernel(const float* __restrict__ emb) {
    int k = threadIdx.x;            // 0..255
    const float4* row = (const float4*)(emb + (size_t)k * LD);
    float s = 0.f;
#pragma unroll
    for (int q = 0; q < LD / 4; q++) {
        float4 v = row[q];
        s = fmaf(v.x, v.x, s);
        s = fmaf(v.y, v.y, s);
        s = fmaf(v.z, v.z, s);
        s = fmaf(v.w, v.w, s);
    }
    g_esq[k] = s;
}

// ---------------------------------------------------------------------------
// f32x2 helpers (Blackwell packed fp32: 2 FMAs per instruction)
// ---------------------------------------------------------------------------
__device__ __forceinline__ unsigned long long pk2(float a, float b) {
    unsigned long long r;
    asm("mov.b64 %0, {%1, %2};" : "=l"(r) : "f"(a), "f"(b));
    return r;
}
__device__ __forceinline__ void upk2(unsigned long long v, float& a, float& b) {
    asm("mov.b64 {%0, %1}, %2;" : "=f"(a), "=f"(b) : "l"(v));
}
__device__ __forceinline__ unsigned long long fma2(unsigned long long a,
                                                   unsigned long long b,
                                                   unsigned long long c) {
    unsigned long long d;
    asm("fma.rn.f32x2 %0, %1, %2, %3;" : "=l"(d) : "l"(a), "l"(b), "l"(c));
    return d;
}

extern __shared__ float smem[];   // [MT*LD] x-tile | [NCH*ES] e-chunk

// ---------------------------------------------------------------------------
// Main kernel: fused GEMM + argmin + gather
// Thread layout: col_t = t & 15 (16 col-threads), row_t = t >> 4 (16 row-threads)
// Thread tile: 8 rows (row_t*8 + i) x 8 cols (col_t + 16*j), FFMA2 over col pairs
// ---------------------------------------------------------------------------
__global__ __launch_bounds__(256, 1)
void vq_kernel(const float* __restrict__ inp, const float* __restrict__ emb,
               float* __restrict__ out) {
    float* sx = smem;              // [MT][LD]  stride LD
    float* se = smem + MT * LD;    // [NCH][ES] stride ES
    const int t     = threadIdx.x;
    const int col_t = t & 15;
    const int row_t = t >> 4;
    const int row0  = row_t * 8;
    const size_t base_row = (size_t)blockIdx.x * MT;

    // ---- load x tile (coalesced float4, conflict-free STS128) ----
    {
        const float4* gin = (const float4*)(inp + base_row * LD);
        float4* sx4 = (float4*)sx;
#pragma unroll
        for (int p = 0; p < (MT * LD / 4) / 256; p++)
            sx4[t + p * 256] = gin[t + p * 256];
    }

    float bestv[8];
    int   besti[8];
#pragma unroll
    for (int i = 0; i < 8; i++) { bestv[i] = 3.4e38f; besti[i] = 0; }

    for (int c = 0; c < 2; c++) {
        __syncthreads();
        // ---- load e chunk into [n][k] stride-ES layout ----
        {
            const float4* ge = (const float4*)(emb + (size_t)c * NCH * LD);
#pragma unroll
            for (int p = 0; p < (NCH * LD / 4) / 256; p++) {
                int fi = t + p * 256;
                int n  = fi >> 5;       // row (embedding)
                int kq = fi & 31;       // float4 index within row
                float4 v = ge[fi];
                float* d = se + n * ES + kq * 4;
                d[0] = v.x; d[1] = v.y; d[2] = v.z; d[3] = v.w;
            }
        }
        __syncthreads();

        unsigned long long acc[8][4];
#pragma unroll
        for (int i = 0; i < 8; i++)
#pragma unroll
            for (int j = 0; j < 4; j++) acc[i][j] = 0ull;

        int nbase[8];
#pragma unroll
        for (int j = 0; j < 8; j++) nbase[j] = (col_t + 16 * j) * ES;

        for (int kk = 0; kk < LD; kk += 4) {
            // x: 8 LDS128 (2 unique addrs/warp -> broadcast, conflict-free)
            float4 xv[8];
#pragma unroll
            for (int i = 0; i < 8; i++)
                xv[i] = *(const float4*)(sx + (row0 + i) * LD + kk);
            // e: 32 scalar LDS (odd stride + interleaved n -> 16 distinct banks)
            float ev[4][8];
#pragma unroll
            for (int j = 0; j < 8; j++) {
                const float* p = se + nbase[j] + kk;
                ev[0][j] = p[0]; ev[1][j] = p[1]; ev[2][j] = p[2]; ev[3][j] = p[3];
            }
#pragma unroll
            for (int q = 0; q < 4; q++) {
                unsigned long long ee[4];
#pragma unroll
                for (int j2 = 0; j2 < 4; j2++)
                    ee[j2] = pk2(ev[q][2 * j2], ev[q][2 * j2 + 1]);
#pragma unroll
                for (int i = 0; i < 8; i++) {
                    float xq = (q == 0) ? xv[i].x : (q == 1) ? xv[i].y
                             : (q == 2) ? xv[i].z : xv[i].w;
                    unsigned long long xx = pk2(xq, xq);
#pragma unroll
                    for (int j2 = 0; j2 < 4; j2++)
                        acc[i][j2] = fma2(xx, ee[j2], acc[i][j2]);
                }
            }
        }

        // ---- fold chunk scores into running argmin (ascending n, strict <) ----
#pragma unroll
        for (int i = 0; i < 8; i++) {
#pragma unroll
            for (int j2 = 0; j2 < 4; j2++) {
                float dlo, dhi;
                upk2(acc[i][j2], dlo, dhi);
                int n0 = c * NCH + col_t + 16 * (2 * j2);
                int n1 = c * NCH + col_t + 16 * (2 * j2 + 1);
                float s0 = fmaf(-2.f, dlo, g_esq[n0]);
                float s1 = fmaf(-2.f, dhi, g_esq[n1]);
                if (s0 < bestv[i]) { bestv[i] = s0; besti[i] = n0; }
                if (s1 < bestv[i]) { bestv[i] = s1; besti[i] = n1; }
            }
        }
    }

    // ---- cross-thread argmin: orderable-key min with lowest-index tiebreak ----
    __syncthreads();
    unsigned long long* keys = (unsigned long long*)smem;  // reuse x-tile space
#pragma unroll
    for (int i = 0; i < 8; i++) {
        unsigned u = __float_as_uint(bestv[i]);
        u = (u & 0x80000000u) ? ~u : (u | 0x80000000u);    // monotone map
        keys[(row0 + i) * 16 + col_t] =
            ((unsigned long long)u << 32) | (unsigned)besti[i];
    }
    __syncthreads();
    __shared__ int sidx[MT];
    if (t < MT) {
        unsigned long long m = keys[t * 16];
#pragma unroll
        for (int c2 = 1; c2 < 16; c2++) {
            unsigned long long v = keys[t * 16 + c2];
            if (v < m) m = v;
        }
        sidx[t] = (int)(m & 0xFFFFFFFFull);
    }
    __syncthreads();

    // ---- gather: out[row] = embeddings[idx[row]] ----
    {
        int r = t >> 1, half = t & 1;
        const float4* src = (const float4*)(emb + (size_t)sidx[r] * LD) + half * 16;
        float4* dst = (float4*)(out + (base_row + r) * LD) + half * 16;
#pragma unroll
        for (int q = 0; q < 16; q++) dst[q] = src[q];
    }
}

// ---------------------------------------------------------------------------
extern "C" void kernel_launch(void* const* d_in, const int* in_sizes, int n_in,
                              void* d_out, int out_size) {
    // inputs is the big tensor, embeddings the small one (robust to ordering)
    int ii = 0, ei = 1;
    if (n_in > 1 && in_sizes[0] < in_sizes[1]) { ii = 1; ei = 0; }
    const float* inp = (const float*)d_in[ii];
    const float* emb = (const float*)d_in[ei];
    float* out = (float*)d_out;

    int rows = in_sizes[ii] / LD;          // 65536
    int grid = rows / MT;                  // 512

    esq_kernel<<<1, 256>>>(emb);

    int smem_bytes = (MT * LD + NCH * ES) * (int)sizeof(float);  // 131584
    static int smem_ok = -1;
    if (smem_ok < 0) {
        cudaError_t e = cudaFuncSetAttribute(
            vq_kernel, cudaFuncAttributeMaxDynamicSharedMemorySize, smem_bytes);
        smem_ok = (e == cudaSuccess) ? 1 : 0;
    }
    vq_kernel<<<grid, 256, smem_bytes>>>(inp, emb, out);
}